// round 16
// baseline (speedup 1.0000x reference)
#include <cuda_runtime.h>
#include <cuda_fp16.h>
#include <cstdint>

// ---------------- problem constants ----------------
#define NEXP   8
#define DDIM   1024
#define HDIM   2048
#define TMAX   8192
#define BM     128
#define BN     128
#define BK     32            // k-halves per stage
#define SLOT_MAX (2*TMAX + NEXP*BM)   // 17408
#define NSTAGE 5
#define ROWB   80            // A smem row pitch bytes (64 data + 16 pad)
#define ASTG   (BM * ROWB)   // 10240 B
#define BROWB  256           // B smem row bytes (128 halves)
#define BSTG   (BK * BROWB)  // 8192 B
#define STGB   (ASTG + BSTG) // 18432 B
#define SMEM_GEMM (NSTAGE * STGB)     // 92160 B -> 2 CTAs/SM

// ---------------- device scratch ----------------
__device__ int    g_counts[NEXP];
__device__ int    g_fill[NEXP];
__device__ int    g_off[NEXP + 1];
__device__ int    g_tok[SLOT_MAX];
__device__ int    g_slot[2 * TMAX];
__device__ int    g_e[2 * TMAX];
__device__ float  g_wt[2 * TMAX];
__device__ __half g_h[(size_t)SLOT_MAX * HDIM];      // fp16 hidden acts
__device__ float  g_y[(size_t)SLOT_MAX * DDIM];      // fp32 expert outputs
__device__ __half g_xh[(size_t)TMAX * DDIM];         // fp16 x
__device__ __half g_w1h[(size_t)NEXP * DDIM * HDIM]; // W1 fp16 [E][D][H]
__device__ __half g_w2h[(size_t)NEXP * HDIM * DDIM]; // W2 fp16 [E][H][D]

// ---------------- helpers ----------------
__device__ __forceinline__ void cp16(uint32_t dst, const void* src, bool valid) {
    int sz = valid ? 16 : 0;
    asm volatile("cp.async.cg.shared.global [%0], [%1], 16, %2;\n"
                 :: "r"(dst), "l"(src), "r"(sz));
}
__device__ __forceinline__ void cp_commit() {
    asm volatile("cp.async.commit_group;\n" ::: "memory");
}
template <int N>
__device__ __forceinline__ void cp_wait() {
    asm volatile("cp.async.wait_group %0;\n" :: "n"(N) : "memory");
}
__device__ __forceinline__ void ldsm4(uint32_t& r0, uint32_t& r1, uint32_t& r2, uint32_t& r3,
                                      uint32_t addr) {
    asm volatile("ldmatrix.sync.aligned.m8n8.x4.shared.b16 {%0,%1,%2,%3}, [%4];"
                 : "=r"(r0), "=r"(r1), "=r"(r2), "=r"(r3) : "r"(addr));
}
__device__ __forceinline__ void ldsm4t(uint32_t& r0, uint32_t& r1, uint32_t& r2, uint32_t& r3,
                                       uint32_t addr) {
    asm volatile("ldmatrix.sync.aligned.m8n8.x4.trans.shared.b16 {%0,%1,%2,%3}, [%4];"
                 : "=r"(r0), "=r"(r1), "=r"(r2), "=r"(r3) : "r"(addr));
}
__device__ __forceinline__ void mma_f16(float& c0, float& c1, float& c2, float& c3,
                                        uint32_t a0, uint32_t a1, uint32_t a2, uint32_t a3,
                                        uint32_t b0, uint32_t b1) {
    asm volatile(
        "mma.sync.aligned.m16n8k16.row.col.f32.f16.f16.f32 "
        "{%0,%1,%2,%3}, {%4,%5,%6,%7}, {%8,%9}, {%0,%1,%2,%3};"
        : "+f"(c0), "+f"(c1), "+f"(c2), "+f"(c3)
        : "r"(a0), "r"(a1), "r"(a2), "r"(a3), "r"(b0), "r"(b1));
}

// ---------------- init ----------------
__global__ void init_kernel() {
    int i = threadIdx.x;
    if (i < NEXP) { g_counts[i] = 0; g_fill[i] = 0; }
}

// ---------------- fp32 -> fp16 elementwise (x) ----------------
__global__ void cvt_h_kernel(const float* __restrict__ src, __half* __restrict__ dst, int nvec4) {
    int i = blockIdx.x * blockDim.x + threadIdx.x;
    if (i >= nvec4) return;
    float4 v = ((const float4*)src)[i];
    ((__half2*)dst)[2 * i]     = __floats2half2_rn(v.x, v.y);
    ((__half2*)dst)[2 * i + 1] = __floats2half2_rn(v.z, v.w);
}

// ---------------- fp32 -> fp16 for both weight tensors (one launch) ----------
__global__ void cvt_w_kernel(const float* __restrict__ W1, const float* __restrict__ W2,
                             __half* __restrict__ d1, __half* __restrict__ d2, int nvec4each) {
    int i = blockIdx.x * blockDim.x + threadIdx.x;
    const float* s; __half* d; int j;
    if (i < nvec4each) { s = W1; d = d1; j = i; }
    else if (i < 2 * nvec4each) { s = W2; d = d2; j = i - nvec4each; }
    else return;
    float4 v = ((const float4*)s)[j];
    ((__half2*)d)[2 * j]     = __floats2half2_rn(v.x, v.y);
    ((__half2*)d)[2 * j + 1] = __floats2half2_rn(v.z, v.w);
}

// ---------------- router: smem-cached Wg, 32 tokens/block (4 per warp) -------
__global__ void router_kernel(const float* __restrict__ x,
                              const float* __restrict__ Wg, int T) {
    __shared__ float sW[NEXP][DDIM];   // 32 KB transposed gate weights
    int tid = threadIdx.x;
    for (int i = tid; i < DDIM * NEXP; i += blockDim.x) {
        int d = i >> 3, e = i & 7;     // Wg is [D][E]
        sW[e][d] = Wg[i];
    }
    __syncthreads();

    int wid  = tid >> 5;
    int lane = tid & 31;

    #pragma unroll 1
    for (int tk = 0; tk < 4; tk++) {
        int tok = blockIdx.x * 32 + wid * 4 + tk;
        if (tok >= T) break;
        const float4* xr = (const float4*)(x + (size_t)tok * DDIM);

        float acc[NEXP];
        #pragma unroll
        for (int e = 0; e < NEXP; e++) acc[e] = 0.f;
        for (int j = lane; j < DDIM / 4; j += 32) {
            float4 v = xr[j];
            #pragma unroll
            for (int e = 0; e < NEXP; e++) {
                float4 w = *(const float4*)&sW[e][4 * j];
                acc[e] += v.x * w.x + v.y * w.y + v.z * w.z + v.w * w.w;
            }
        }
        #pragma unroll
        for (int e = 0; e < NEXP; e++) {
            #pragma unroll
            for (int o = 16; o > 0; o >>= 1)
                acc[e] += __shfl_xor_sync(0xffffffffu, acc[e], o);
        }
        if (lane == 0) {
            int b0 = 0; float l0 = acc[0];
            #pragma unroll
            for (int e = 1; e < NEXP; e++)
                if (acc[e] > l0) { l0 = acc[e]; b0 = e; }
            int b1 = -1; float l1 = -3.0e38f;
            #pragma unroll
            for (int e = 0; e < NEXP; e++)
                if (e != b0 && acc[e] > l1) { l1 = acc[e]; b1 = e; }
            float w1 = 1.0f / (1.0f + expf(l0 - l1));
            float w0 = 1.0f - w1;
            g_e[2 * tok]     = b0;  g_e[2 * tok + 1]  = b1;
            g_wt[2 * tok]    = w0;  g_wt[2 * tok + 1] = w1;
            atomicAdd(&g_counts[b0], 1);
            atomicAdd(&g_counts[b1], 1);
        }
    }
}

// ---------------- offsets ----------------
__global__ void offsets_kernel() {
    if (threadIdx.x == 0) {
        g_off[0] = 0;
        #pragma unroll
        for (int e = 0; e < NEXP; e++) {
            int c = g_counts[e];
            g_off[e + 1] = g_off[e] + ((c + BM - 1) / BM) * BM;
            g_fill[e] = 0;
        }
    }
}

// ---------------- scatter ----------------
__global__ void scatter_kernel(int T) {
    int t = blockIdx.x * blockDim.x + threadIdx.x;
    if (t >= T) return;
    #pragma unroll
    for (int k = 0; k < 2; k++) {
        int e   = g_e[2 * t + k];
        int pos = atomicAdd(&g_fill[e], 1);
        int slot = g_off[e] + pos;
        g_tok[slot]       = t;
        g_slot[2 * t + k] = slot;
    }
}

// ---------------- grouped GEMM: fp16 mma + ldmatrix(.trans B), 128x128 -------
// 256 threads, 8 warps (4m x 2n, warp tile 32x64), 5-stage cp.async ring with
// prefetch distance 4, 92 KB smem -> 2 CTAs/SM.
template <int KDIM, int NDIM, bool GATHER, bool RELU>
__global__ void __launch_bounds__(256, 2)
gemm_f16(const __half* __restrict__ Asrc,
         const __half* __restrict__ Wh,     // [E][KDIM][NDIM] fp16
         const float* __restrict__ bias) {  // [E][NDIM]
    extern __shared__ uint8_t smb[];

    int r0 = blockIdx.x * BM;
    int totalRows = g_off[NEXP];
    if (r0 >= totalRows) return;
    int n0 = blockIdx.y * BN;

    int e = 0;
    #pragma unroll
    for (int i = 0; i < NEXP; i++)
        if (r0 >= g_off[i + 1]) e = i + 1;
    int cnt = g_counts[e], base = g_off[e];

    int tid  = threadIdx.x;
    int wid  = tid >> 5;
    int lane = tid & 31;
    int g    = lane >> 2;
    int q    = lane & 3;
    int warpM = (wid & 3) * 32;         // 0,32,64,96
    int warpN = (wid >> 2) * 64;        // 0,64

    uint32_t smem_base = (uint32_t)__cvta_generic_to_shared(smb);

    // ---- A loader: 128 rows x 4 chunks(16B) = 512 -> 2 per thread ----
    int aLrow = tid >> 1, aLc = tid & 1;        // chunks aLc, aLc+2
    const __half* aRowP;
    bool aValid = true;
    if (GATHER) {
        int slot = r0 + aLrow;
        aValid = (unsigned)(slot - base) < (unsigned)cnt;
        aRowP = Asrc + (size_t)(aValid ? g_tok[slot] : 0) * KDIM + aLc * 8;
    } else {
        aRowP = g_h + (size_t)(r0 + aLrow) * KDIM + aLc * 8;
    }
    uint32_t aDst = smem_base + aLrow * ROWB + aLc * 16;

    // ---- B loader: 32 k-rows x 16 chunks(16B) = 512 -> 2 per thread ----
    int bLk = tid >> 3;                 // 0..31
    int bLc = (tid & 7) * 2;            // chunks bLc, bLc+1
    const __half* bRowP = Wh + (size_t)e * KDIM * NDIM + (size_t)bLk * NDIM + n0 + bLc * 8;
    uint32_t bBase = smem_base + ASTG + bLk * BROWB;
    uint32_t bDst0 = bBase + ((bLc     ^ (bLk & 7)) * 16);
    uint32_t bDst1 = bBase + (((bLc+1) ^ (bLk & 7)) * 16);

    auto issue = [&](int t) {
        uint32_t sb = (t % NSTAGE) * STGB;
        int k0 = t * BK;
        cp16(aDst + sb,      aRowP + k0, aValid);
        cp16(aDst + sb + 32, aRowP + k0 + 16, aValid);     // chunk +2
        cp16(bDst0 + sb, bRowP + (size_t)k0 * NDIM, true);
        cp16(bDst1 + sb, bRowP + (size_t)k0 * NDIM + 8, true);
        cp_commit();
    };

    // ---- A fragment addressing (non-trans ldmatrix) ----
    int arow = (lane & 7) | (((lane >> 3) & 1) << 3);
    int aksel = (lane >> 4) & 1;
    uint32_t aFrag = smem_base + (warpM + arow) * ROWB + aksel * 16;

    // ---- B fragment addressing (trans ldmatrix, swizzled) ----
    int mrow  = lane & 7;
    int khigh = (lane >> 3) & 1;        // +8 k
    int csel  = (lane >> 4) & 1;        // +1 chunk (8 n)

    float acc[2][8][4];
    #pragma unroll
    for (int mf = 0; mf < 2; mf++)
        #pragma unroll
        for (int nf = 0; nf < 8; nf++)
            #pragma unroll
            for (int c = 0; c < 4; c++) acc[mf][nf][c] = 0.f;

    const int NT = KDIM / BK;
    issue(0); issue(1); issue(2); issue(3);

    for (int t = 0; t < NT; t++) {
        uint32_t sb = (t % NSTAGE) * STGB;
        if (t + 4 <= NT) cp_wait<3>();
        else if (t + 3 == NT) cp_wait<2>();
        else if (t + 2 == NT) cp_wait<1>();
        else cp_wait<0>();
        __syncthreads();
        if (t + 4 < NT) issue(t + 4);

        #pragma unroll
        for (int ks = 0; ks < 2; ks++) {
            int kb = ks * 16 + khigh * 8 + mrow;          // this lane's absolute k row
            uint32_t bRow = smem_base + ASTG + sb + kb * BROWB;
            uint32_t afr[2][4], bfr[4][4];
            #pragma unroll
            for (int mf = 0; mf < 2; mf++)
                ldsm4(afr[mf][0], afr[mf][1], afr[mf][2], afr[mf][3],
                      aFrag + sb + mf * 16 * ROWB + ks * 32);
            #pragma unroll
            for (int nh = 0; nh < 4; nh++) {
                int c = (warpN + nh * 16) / 8 + csel;
                ldsm4t(bfr[nh][0], bfr[nh][1], bfr[nh][2], bfr[nh][3],
                       bRow + ((c ^ (kb & 7)) * 16));
            }
            #pragma unroll
            for (int mf = 0; mf < 2; mf++)
                #pragma unroll
                for (int nh = 0; nh < 4; nh++) {
                    mma_f16(acc[mf][2*nh][0], acc[mf][2*nh][1],
                            acc[mf][2*nh][2], acc[mf][2*nh][3],
                            afr[mf][0], afr[mf][1], afr[mf][2], afr[mf][3],
                            bfr[nh][0], bfr[nh][1]);
                    mma_f16(acc[mf][2*nh+1][0], acc[mf][2*nh+1][1],
                            acc[mf][2*nh+1][2], acc[mf][2*nh+1][3],
                            afr[mf][0], afr[mf][1], afr[mf][2], afr[mf][3],
                            bfr[nh][2], bfr[nh][3]);
                }
        }
    }

    // ---- epilogue: bias (+relu) ----
    const float* be = bias + (size_t)e * NDIM;
    #pragma unroll
    for (int mf = 0; mf < 2; mf++) {
        int row0 = r0 + warpM + mf * 16 + g;
        int row1 = row0 + 8;
        #pragma unroll
        for (int nf = 0; nf < 8; nf++) {
            int col = n0 + warpN + nf * 8 + q * 2;
            float bv0 = be[col], bv1 = be[col + 1];
            float v00 = acc[mf][nf][0] + bv0, v01 = acc[mf][nf][1] + bv1;
            float v10 = acc[mf][nf][2] + bv0, v11 = acc[mf][nf][3] + bv1;
            if (RELU) {
                v00 = fmaxf(v00, 0.f); v01 = fmaxf(v01, 0.f);
                v10 = fmaxf(v10, 0.f); v11 = fmaxf(v11, 0.f);
            }
            if (GATHER) {
                *(__half2*)(g_h + (size_t)row0 * NDIM + col) = __floats2half2_rn(v00, v01);
                *(__half2*)(g_h + (size_t)row1 * NDIM + col) = __floats2half2_rn(v10, v11);
            } else {
                *(float2*)(g_y + (size_t)row0 * NDIM + col) = make_float2(v00, v01);
                *(float2*)(g_y + (size_t)row1 * NDIM + col) = make_float2(v10, v11);
            }
        }
    }
}

// ---------------- combine ----------------
__global__ void combine_kernel(float* __restrict__ out, int T) {
    int i = blockIdx.x * blockDim.x + threadIdx.x;
    int nvec = T * (DDIM / 4);
    if (i >= nvec) return;
    int t = i / (DDIM / 4);
    int j = i % (DDIM / 4);
    int s0 = g_slot[2 * t], s1 = g_slot[2 * t + 1];
    float w0 = g_wt[2 * t], w1 = g_wt[2 * t + 1];
    float4 y0 = ((const float4*)(g_y + (size_t)s0 * DDIM))[j];
    float4 y1 = ((const float4*)(g_y + (size_t)s1 * DDIM))[j];
    float4 o;
    o.x = w0 * y0.x + w1 * y1.x;
    o.y = w0 * y0.y + w1 * y1.y;
    o.z = w0 * y0.z + w1 * y1.z;
    o.w = w0 * y0.w + w1 * y1.w;
    ((float4*)out)[i] = o;
}

// ---------------- launch ----------------
extern "C" void kernel_launch(void* const* d_in, const int* in_sizes, int n_in,
                              void* d_out, int out_size) {
    const float* x  = (const float*)d_in[0];
    const float* Wg = (const float*)d_in[1];
    const float* W1 = (const float*)d_in[2];
    const float* b1 = (const float*)d_in[3];
    const float* W2 = (const float*)d_in[4];
    const float* b2 = (const float*)d_in[5];
    float* out = (float*)d_out;
    int T = in_sizes[0] / DDIM;   // 8192

    __half *s_xh, *s_w1h, *s_w2h;
    cudaGetSymbolAddress((void**)&s_xh,  g_xh);
    cudaGetSymbolAddress((void**)&s_w1h, g_w1h);
    cudaGetSymbolAddress((void**)&s_w2h, g_w2h);
    cudaFuncSetAttribute(gemm_f16<DDIM, HDIM, true,  true >,
                         cudaFuncAttributeMaxDynamicSharedMemorySize, SMEM_GEMM);
    cudaFuncSetAttribute(gemm_f16<HDIM, DDIM, false, false>,
                         cudaFuncAttributeMaxDynamicSharedMemorySize, SMEM_GEMM);

    init_kernel<<<1, 32>>>();

    int nx = T * DDIM / 4;
    cvt_h_kernel<<<(nx + 255) / 256, 256>>>(x, s_xh, nx);
    int nw = NEXP * DDIM * HDIM / 4;
    cvt_w_kernel<<<(2 * nw + 255) / 256, 256>>>(W1, W2, s_w1h, s_w2h, nw);

    router_kernel<<<(T + 31) / 32, 256>>>(x, Wg, T);
    offsets_kernel<<<1, 32>>>();
    scatter_kernel<<<(T + 255) / 256, 256>>>(T);

    dim3 grid1(SLOT_MAX / BM, HDIM / BN);   // 136 x 16
    gemm_f16<DDIM, HDIM, true,  true ><<<grid1, 256, SMEM_GEMM>>>(s_xh, s_w1h, b1);

    dim3 grid2(SLOT_MAX / BM, DDIM / BN);   // 136 x 8
    gemm_f16<HDIM, DDIM, false, false><<<grid2, 256, SMEM_GEMM>>>(nullptr, s_w2h, b2);

    int nvec = T * (DDIM / 4);
    combine_kernel<<<(nvec + 255) / 256, 256>>>(out, T);
}

// round 17
// speedup vs baseline: 1.0270x; 1.0270x over previous
#include <cuda_runtime.h>
#include <cuda_fp16.h>
#include <cstdint>

// ---------------- problem constants ----------------
#define NEXP   8
#define DDIM   1024
#define HDIM   2048
#define TMAX   8192
#define BM     128
#define BN     128
#define BK     32            // k-halves per stage
#define SLOT_MAX (2*TMAX + NEXP*BM)   // 17408
#define NSTAGE 4
#define ROWB   80            // A smem row pitch bytes (64 data + 16 pad)
#define ASTG   (BM * ROWB)   // 10240 B
#define BROWB  256           // B smem row bytes (128 halves)
#define BSTG   (BK * BROWB)  // 8192 B
#define STGB   (ASTG + BSTG) // 18432 B
#define SMEM_GEMM (NSTAGE * STGB)     // 73728 B -> 2 CTAs/SM

// ---------------- device scratch ----------------
__device__ int    g_counts[NEXP];
__device__ int    g_fill[NEXP];
__device__ int    g_off[NEXP + 1];
__device__ int    g_tok[SLOT_MAX];
__device__ int    g_slot[2 * TMAX];
__device__ int    g_e[2 * TMAX];
__device__ float  g_wt[2 * TMAX];
__device__ __half g_h[(size_t)SLOT_MAX * HDIM];      // fp16 hidden acts
__device__ __half g_y[(size_t)SLOT_MAX * DDIM];      // fp16 expert outputs
__device__ __half g_xh[(size_t)TMAX * DDIM];         // fp16 x
__device__ __half g_w1h[(size_t)NEXP * DDIM * HDIM]; // W1 fp16 [E][D][H]
__device__ __half g_w2h[(size_t)NEXP * HDIM * DDIM]; // W2 fp16 [E][H][D]

// ---------------- helpers ----------------
__device__ __forceinline__ void cp16(uint32_t dst, const void* src, bool valid) {
    int sz = valid ? 16 : 0;
    asm volatile("cp.async.cg.shared.global [%0], [%1], 16, %2;\n"
                 :: "r"(dst), "l"(src), "r"(sz));
}
__device__ __forceinline__ void cp_commit() {
    asm volatile("cp.async.commit_group;\n" ::: "memory");
}
template <int N>
__device__ __forceinline__ void cp_wait() {
    asm volatile("cp.async.wait_group %0;\n" :: "n"(N) : "memory");
}
__device__ __forceinline__ void ldsm4(uint32_t& r0, uint32_t& r1, uint32_t& r2, uint32_t& r3,
                                      uint32_t addr) {
    asm volatile("ldmatrix.sync.aligned.m8n8.x4.shared.b16 {%0,%1,%2,%3}, [%4];"
                 : "=r"(r0), "=r"(r1), "=r"(r2), "=r"(r3) : "r"(addr));
}
__device__ __forceinline__ void ldsm4t(uint32_t& r0, uint32_t& r1, uint32_t& r2, uint32_t& r3,
                                       uint32_t addr) {
    asm volatile("ldmatrix.sync.aligned.m8n8.x4.trans.shared.b16 {%0,%1,%2,%3}, [%4];"
                 : "=r"(r0), "=r"(r1), "=r"(r2), "=r"(r3) : "r"(addr));
}
__device__ __forceinline__ void mma_f16(float& c0, float& c1, float& c2, float& c3,
                                        uint32_t a0, uint32_t a1, uint32_t a2, uint32_t a3,
                                        uint32_t b0, uint32_t b1) {
    asm volatile(
        "mma.sync.aligned.m16n8k16.row.col.f32.f16.f16.f32 "
        "{%0,%1,%2,%3}, {%4,%5,%6,%7}, {%8,%9}, {%0,%1,%2,%3};"
        : "+f"(c0), "+f"(c1), "+f"(c2), "+f"(c3)
        : "r"(a0), "r"(a1), "r"(a2), "r"(a3), "r"(b0), "r"(b1));
}

// ---------------- init ----------------
__global__ void init_kernel() {
    int i = threadIdx.x;
    if (i < NEXP) { g_counts[i] = 0; g_fill[i] = 0; }
}

// ---------------- fp32 -> fp16 elementwise (x) ----------------
__global__ void cvt_h_kernel(const float* __restrict__ src, __half* __restrict__ dst, int nvec4) {
    int i = blockIdx.x * blockDim.x + threadIdx.x;
    if (i >= nvec4) return;
    float4 v = ((const float4*)src)[i];
    ((__half2*)dst)[2 * i]     = __floats2half2_rn(v.x, v.y);
    ((__half2*)dst)[2 * i + 1] = __floats2half2_rn(v.z, v.w);
}

// ---------------- fp32 -> fp16 for both weight tensors (one launch) ----------
__global__ void cvt_w_kernel(const float* __restrict__ W1, const float* __restrict__ W2,
                             __half* __restrict__ d1, __half* __restrict__ d2, int nvec4each) {
    int i = blockIdx.x * blockDim.x + threadIdx.x;
    const float* s; __half* d; int j;
    if (i < nvec4each) { s = W1; d = d1; j = i; }
    else if (i < 2 * nvec4each) { s = W2; d = d2; j = i - nvec4each; }
    else return;
    float4 v = ((const float4*)s)[j];
    ((__half2*)d)[2 * j]     = __floats2half2_rn(v.x, v.y);
    ((__half2*)d)[2 * j + 1] = __floats2half2_rn(v.z, v.w);
}

// ---------------- router: smem-cached Wg, 16 tokens/block (2 per warp) -------
__global__ void router_kernel(const float* __restrict__ x,
                              const float* __restrict__ Wg, int T) {
    __shared__ float sW[NEXP][DDIM];   // 32 KB transposed gate weights
    int tid = threadIdx.x;
    for (int i = tid; i < DDIM * NEXP; i += blockDim.x) {
        int d = i >> 3, e = i & 7;     // Wg is [D][E]
        sW[e][d] = Wg[i];
    }
    __syncthreads();

    int wid  = tid >> 5;
    int lane = tid & 31;

    #pragma unroll 1
    for (int tk = 0; tk < 2; tk++) {
        int tok = blockIdx.x * 16 + wid * 2 + tk;
        if (tok >= T) break;
        const float4* xr = (const float4*)(x + (size_t)tok * DDIM);

        float acc[NEXP];
        #pragma unroll
        for (int e = 0; e < NEXP; e++) acc[e] = 0.f;
        for (int j = lane; j < DDIM / 4; j += 32) {
            float4 v = xr[j];
            #pragma unroll
            for (int e = 0; e < NEXP; e++) {
                float4 w = *(const float4*)&sW[e][4 * j];
                acc[e] += v.x * w.x + v.y * w.y + v.z * w.z + v.w * w.w;
            }
        }
        #pragma unroll
        for (int e = 0; e < NEXP; e++) {
            #pragma unroll
            for (int o = 16; o > 0; o >>= 1)
                acc[e] += __shfl_xor_sync(0xffffffffu, acc[e], o);
        }
        if (lane == 0) {
            int b0 = 0; float l0 = acc[0];
            #pragma unroll
            for (int e = 1; e < NEXP; e++)
                if (acc[e] > l0) { l0 = acc[e]; b0 = e; }
            int b1 = -1; float l1 = -3.0e38f;
            #pragma unroll
            for (int e = 0; e < NEXP; e++)
                if (e != b0 && acc[e] > l1) { l1 = acc[e]; b1 = e; }
            float w1 = 1.0f / (1.0f + expf(l0 - l1));
            float w0 = 1.0f - w1;
            g_e[2 * tok]     = b0;  g_e[2 * tok + 1]  = b1;
            g_wt[2 * tok]    = w0;  g_wt[2 * tok + 1] = w1;
            atomicAdd(&g_counts[b0], 1);
            atomicAdd(&g_counts[b1], 1);
        }
    }
}

// ---------------- offsets ----------------
__global__ void offsets_kernel() {
    if (threadIdx.x == 0) {
        g_off[0] = 0;
        #pragma unroll
        for (int e = 0; e < NEXP; e++) {
            int c = g_counts[e];
            g_off[e + 1] = g_off[e] + ((c + BM - 1) / BM) * BM;
            g_fill[e] = 0;
        }
    }
}

// ---------------- scatter ----------------
__global__ void scatter_kernel(int T) {
    int t = blockIdx.x * blockDim.x + threadIdx.x;
    if (t >= T) return;
    #pragma unroll
    for (int k = 0; k < 2; k++) {
        int e   = g_e[2 * t + k];
        int pos = atomicAdd(&g_fill[e], 1);
        int slot = g_off[e] + pos;
        g_tok[slot]       = t;
        g_slot[2 * t + k] = slot;
    }
}

// ---------------- grouped GEMM: fp16 mma + ldmatrix(.trans B), 128x128 -------
// R14-proven config: 256 threads, 8 warps (4m x 2n), 4-stage cp.async ring,
// 73.7 KB smem -> 2 CTAs/SM. Epilogue always stores fp16 (g_h or g_y).
template <int KDIM, int NDIM, bool GATHER, bool RELU>
__global__ void __launch_bounds__(256, 2)
gemm_f16(const __half* __restrict__ Asrc,
         const __half* __restrict__ Wh,     // [E][KDIM][NDIM] fp16
         const float* __restrict__ bias) {  // [E][NDIM]
    extern __shared__ uint8_t smb[];

    int r0 = blockIdx.x * BM;
    int totalRows = g_off[NEXP];
    if (r0 >= totalRows) return;
    int n0 = blockIdx.y * BN;

    int e = 0;
    #pragma unroll
    for (int i = 0; i < NEXP; i++)
        if (r0 >= g_off[i + 1]) e = i + 1;
    int cnt = g_counts[e], base = g_off[e];

    int tid  = threadIdx.x;
    int wid  = tid >> 5;
    int lane = tid & 31;
    int g    = lane >> 2;
    int q    = lane & 3;
    int warpM = (wid & 3) * 32;         // 0,32,64,96
    int warpN = (wid >> 2) * 64;        // 0,64

    uint32_t smem_base = (uint32_t)__cvta_generic_to_shared(smb);

    // ---- A loader: 128 rows x 4 chunks(16B) = 512 -> 2 per thread ----
    int aLrow = tid >> 1, aLc = tid & 1;        // chunks aLc, aLc+2
    const __half* aRowP;
    bool aValid = true;
    if (GATHER) {
        int slot = r0 + aLrow;
        aValid = (unsigned)(slot - base) < (unsigned)cnt;
        aRowP = Asrc + (size_t)(aValid ? g_tok[slot] : 0) * KDIM + aLc * 8;
    } else {
        aRowP = g_h + (size_t)(r0 + aLrow) * KDIM + aLc * 8;
    }
    uint32_t aDst = smem_base + aLrow * ROWB + aLc * 16;

    // ---- B loader: 32 k-rows x 16 chunks(16B) = 512 -> 2 per thread ----
    int bLk = tid >> 3;                 // 0..31
    int bLc = (tid & 7) * 2;            // chunks bLc, bLc+1
    const __half* bRowP = Wh + (size_t)e * KDIM * NDIM + (size_t)bLk * NDIM + n0 + bLc * 8;
    uint32_t bBase = smem_base + ASTG + bLk * BROWB;
    uint32_t bDst0 = bBase + ((bLc     ^ (bLk & 7)) * 16);
    uint32_t bDst1 = bBase + (((bLc+1) ^ (bLk & 7)) * 16);

    auto issue = [&](int t) {
        uint32_t sb = (t % NSTAGE) * STGB;
        int k0 = t * BK;
        cp16(aDst + sb,      aRowP + k0, aValid);
        cp16(aDst + sb + 32, aRowP + k0 + 16, aValid);     // chunk +2
        cp16(bDst0 + sb, bRowP + (size_t)k0 * NDIM, true);
        cp16(bDst1 + sb, bRowP + (size_t)k0 * NDIM + 8, true);
        cp_commit();
    };

    // ---- A fragment addressing (non-trans ldmatrix) ----
    int arow = (lane & 7) | (((lane >> 3) & 1) << 3);
    int aksel = (lane >> 4) & 1;
    uint32_t aFrag = smem_base + (warpM + arow) * ROWB + aksel * 16;

    // ---- B fragment addressing (trans ldmatrix, swizzled) ----
    int mrow  = lane & 7;
    int khigh = (lane >> 3) & 1;        // +8 k
    int csel  = (lane >> 4) & 1;        // +1 chunk (8 n)

    float acc[2][8][4];
    #pragma unroll
    for (int mf = 0; mf < 2; mf++)
        #pragma unroll
        for (int nf = 0; nf < 8; nf++)
            #pragma unroll
            for (int c = 0; c < 4; c++) acc[mf][nf][c] = 0.f;

    const int NT = KDIM / BK;
    issue(0); issue(1); issue(2);

    for (int t = 0; t < NT; t++) {
        uint32_t sb = (t % NSTAGE) * STGB;
        if (t + 3 <= NT) cp_wait<2>();
        else if (t + 2 == NT) cp_wait<1>();
        else cp_wait<0>();
        __syncthreads();
        if (t + 3 < NT) issue(t + 3);

        #pragma unroll
        for (int ks = 0; ks < 2; ks++) {
            int kb = ks * 16 + khigh * 8 + mrow;          // this lane's absolute k row
            uint32_t bRow = smem_base + ASTG + sb + kb * BROWB;
            uint32_t afr[2][4], bfr[4][4];
            #pragma unroll
            for (int mf = 0; mf < 2; mf++)
                ldsm4(afr[mf][0], afr[mf][1], afr[mf][2], afr[mf][3],
                      aFrag + sb + mf * 16 * ROWB + ks * 32);
            #pragma unroll
            for (int nh = 0; nh < 4; nh++) {
                int c = (warpN + nh * 16) / 8 + csel;
                ldsm4t(bfr[nh][0], bfr[nh][1], bfr[nh][2], bfr[nh][3],
                       bRow + ((c ^ (kb & 7)) * 16));
            }
            #pragma unroll
            for (int mf = 0; mf < 2; mf++)
                #pragma unroll
                for (int nh = 0; nh < 4; nh++) {
                    mma_f16(acc[mf][2*nh][0], acc[mf][2*nh][1],
                            acc[mf][2*nh][2], acc[mf][2*nh][3],
                            afr[mf][0], afr[mf][1], afr[mf][2], afr[mf][3],
                            bfr[nh][0], bfr[nh][1]);
                    mma_f16(acc[mf][2*nh+1][0], acc[mf][2*nh+1][1],
                            acc[mf][2*nh+1][2], acc[mf][2*nh+1][3],
                            afr[mf][0], afr[mf][1], afr[mf][2], afr[mf][3],
                            bfr[nh][2], bfr[nh][3]);
                }
        }
    }

    // ---- epilogue: bias (+relu), fp16 store ----
    const float* be = bias + (size_t)e * NDIM;
    __half* OutBuf = GATHER ? g_h : g_y;
    #pragma unroll
    for (int mf = 0; mf < 2; mf++) {
        int row0 = r0 + warpM + mf * 16 + g;
        int row1 = row0 + 8;
        #pragma unroll
        for (int nf = 0; nf < 8; nf++) {
            int col = n0 + warpN + nf * 8 + q * 2;
            float bv0 = be[col], bv1 = be[col + 1];
            float v00 = acc[mf][nf][0] + bv0, v01 = acc[mf][nf][1] + bv1;
            float v10 = acc[mf][nf][2] + bv0, v11 = acc[mf][nf][3] + bv1;
            if (RELU) {
                v00 = fmaxf(v00, 0.f); v01 = fmaxf(v01, 0.f);
                v10 = fmaxf(v10, 0.f); v11 = fmaxf(v11, 0.f);
            }
            *(__half2*)(OutBuf + (size_t)row0 * NDIM + col) = __floats2half2_rn(v00, v01);
            *(__half2*)(OutBuf + (size_t)row1 * NDIM + col) = __floats2half2_rn(v10, v11);
        }
    }
}

// ---------------- combine: out[t] = w0*y16[slot0] + w1*y16[slot1] ------------
__global__ void combine_kernel(float* __restrict__ out, int T) {
    int i = blockIdx.x * blockDim.x + threadIdx.x;
    int nvec = T * (DDIM / 4);
    if (i >= nvec) return;
    int t = i / (DDIM / 4);
    int j = i % (DDIM / 4);
    int s0 = g_slot[2 * t], s1 = g_slot[2 * t + 1];
    float w0 = g_wt[2 * t], w1 = g_wt[2 * t + 1];
    const __half2* y0 = (const __half2*)(g_y + (size_t)s0 * DDIM) + 2 * j;
    const __half2* y1 = (const __half2*)(g_y + (size_t)s1 * DDIM) + 2 * j;
    float2 a0 = __half22float2(y0[0]), b0 = __half22float2(y0[1]);
    float2 a1 = __half22float2(y1[0]), b1 = __half22float2(y1[1]);
    float4 o;
    o.x = w0 * a0.x + w1 * a1.x;
    o.y = w0 * a0.y + w1 * a1.y;
    o.z = w0 * b0.x + w1 * b1.x;
    o.w = w0 * b0.y + w1 * b1.y;
    ((float4*)out)[i] = o;
}

// ---------------- launch ----------------
extern "C" void kernel_launch(void* const* d_in, const int* in_sizes, int n_in,
                              void* d_out, int out_size) {
    const float* x  = (const float*)d_in[0];
    const float* Wg = (const float*)d_in[1];
    const float* W1 = (const float*)d_in[2];
    const float* b1 = (const float*)d_in[3];
    const float* W2 = (const float*)d_in[4];
    const float* b2 = (const float*)d_in[5];
    float* out = (float*)d_out;
    int T = in_sizes[0] / DDIM;   // 8192

    __half *s_xh, *s_w1h, *s_w2h;
    cudaGetSymbolAddress((void**)&s_xh,  g_xh);
    cudaGetSymbolAddress((void**)&s_w1h, g_w1h);
    cudaGetSymbolAddress((void**)&s_w2h, g_w2h);
    cudaFuncSetAttribute(gemm_f16<DDIM, HDIM, true,  true >,
                         cudaFuncAttributeMaxDynamicSharedMemorySize, SMEM_GEMM);
    cudaFuncSetAttribute(gemm_f16<HDIM, DDIM, false, false>,
                         cudaFuncAttributeMaxDynamicSharedMemorySize, SMEM_GEMM);

    init_kernel<<<1, 32>>>();

    int nx = T * DDIM / 4;
    cvt_h_kernel<<<(nx + 255) / 256, 256>>>(x, s_xh, nx);
    int nw = NEXP * DDIM * HDIM / 4;
    cvt_w_kernel<<<(2 * nw + 255) / 256, 256>>>(W1, W2, s_w1h, s_w2h, nw);

    router_kernel<<<(T + 15) / 16, 256>>>(x, Wg, T);
    offsets_kernel<<<1, 32>>>();
    scatter_kernel<<<(T + 255) / 256, 256>>>(T);

    dim3 grid1(SLOT_MAX / BM, HDIM / BN);   // 136 x 16
    gemm_f16<DDIM, HDIM, true,  true ><<<grid1, 256, SMEM_GEMM>>>(s_xh, s_w1h, b1);

    dim3 grid2(SLOT_MAX / BM, DDIM / BN);   // 136 x 8
    gemm_f16<HDIM, DDIM, false, false><<<grid2, 256, SMEM_GEMM>>>(nullptr, s_w2h, b2);

    int nvec = T * (DDIM / 4);
    combine_kernel<<<(nvec + 255) / 256, 256>>>(out, T);
}